// round 15
// baseline (speedup 1.0000x reference)
#include <cuda_runtime.h>
#include <cuda_bf16.h>
#include <math.h>
#include <stdint.h>

// Problem constants
#define BATCH   2
#define NTXT    2048
#define T_MEDIA 4
#define M_MEDIA 256
#define TM_TOT  1024
#define DIM     1024
#define HEADS   16
#define DH      64
#define EPS     1e-5f

#define MQ  (BATCH * NTXT)     // 4096
#define MKV (BATCH * TM_TOT)   // 2048
#define SB  8                  // slots batched in qact
#define SBO 4                  // slots batched in out_act

// ---------------------------------------------------------------------------
// Scratch (device globals; no allocations allowed)
// ---------------------------------------------------------------------------
__device__ __nv_bfloat16 g_img_hi[MKV * DIM];
__device__ __nv_bfloat16 g_img_lo[MKV * DIM];
__device__ __nv_bfloat16 g_Wkv_hi[2 * DIM * DIM];
__device__ __nv_bfloat16 g_Wkv_lo[2 * DIM * DIM];

__device__ float g_kv   [MKV * 2 * DIM];           // k | v (fp32)
__device__ float g_vmean[BATCH * DIM];             // SUM of v cols (scaled later)
__device__ float g_omean[BATCH * DIM];             // (vmean/1024) @ Wo (fp32)
__device__ int   g_tt   [MQ];                      // txt_time
__device__ int   g_act  [MQ];                      // active rows (tt in [1..4])
__device__ int   g_nact;
__device__ float g_qact [MQ * DIM];                // q rows for active queries
__device__ float g_oact [MQ * DIM];                // attention out for active queries

// ---------------------------------------------------------------------------
// PTX helpers (sm_80-baseline only; NO tcgen05 — ptxas target lacks 'a')
// ---------------------------------------------------------------------------
__device__ __forceinline__ uint32_t smem_u32(const void* p) {
    uint32_t a;
    asm("{ .reg .u64 t; cvta.to.shared.u64 t, %1; cvt.u32.u64 %0, t; }" : "=r"(a) : "l"(p));
    return a;
}
__device__ __forceinline__ void cp_async16(uint32_t dst, const void* src) {
    asm volatile("cp.async.cg.shared.global [%0], [%1], 16;\n" :: "r"(dst), "l"(src));
}
__device__ __forceinline__ void ldsm4(uint32_t* r, uint32_t addr) {
    asm volatile("ldmatrix.sync.aligned.m8n8.x4.shared.b16 {%0,%1,%2,%3}, [%4];"
                 : "=r"(r[0]), "=r"(r[1]), "=r"(r[2]), "=r"(r[3]) : "r"(addr));
}
__device__ __forceinline__ void mma16816(float* c, const uint32_t* a,
                                         uint32_t b0, uint32_t b1) {
    asm volatile(
        "mma.sync.aligned.m16n8k16.row.col.f32.bf16.bf16.f32 "
        "{%0,%1,%2,%3}, {%4,%5,%6,%7}, {%8,%9}, {%0,%1,%2,%3};"
        : "+f"(c[0]), "+f"(c[1]), "+f"(c[2]), "+f"(c[3])
        : "r"(a[0]), "r"(a[1]), "r"(a[2]), "r"(a[3]), "r"(b0), "r"(b1));
}
__device__ __forceinline__ uint32_t sw128(uint32_t off) {
    return off ^ ((off >> 3) & 0x70);
}
__device__ __forceinline__ void split2(float v, __nv_bfloat16& h, __nv_bfloat16& l) {
    h = __float2bfloat16(v);
    l = __float2bfloat16(v - __bfloat162float(h));
}

// ---------------------------------------------------------------------------
// Scan + compact fused: one block of 1024 threads handles both batches.
// ---------------------------------------------------------------------------
__global__ void scan_compact_kernel(const int* __restrict__ loc) {
    __shared__ int s[1024];
    int tid = threadIdx.x;
    if (tid == 0) g_nact = 0;
    __syncthreads();
    for (int b = 0; b < BATCH; b++) {
        const int* L = loc + b * NTXT;
        int a0 = L[2 * tid];
        int a1 = L[2 * tid + 1];
        int v0 = a0, v1 = a0 + a1;
        s[tid] = v1;
        __syncthreads();
        for (int off = 1; off < 1024; off <<= 1) {
            int t = (tid >= off) ? s[tid - off] : 0;
            __syncthreads();
            s[tid] += t;
            __syncthreads();
        }
        int excl = s[tid] - v1;
        int t0 = excl + v0, t1 = excl + v1;
        int r0 = b * NTXT + 2 * tid, r1 = r0 + 1;
        g_tt[r0] = t0;
        g_tt[r1] = t1;
        if (t0 >= 1 && t0 <= T_MEDIA) g_act[atomicAdd(&g_nact, 1)] = r0;
        if (t1 >= 1 && t1 <= T_MEDIA) g_act[atomicAdd(&g_nact, 1)] = r1;
        __syncthreads();
    }
}

// ---------------------------------------------------------------------------
// Block reduce helper (256 threads)
// ---------------------------------------------------------------------------
__device__ __forceinline__ float blockReduceSum256(float v, float* red) {
    #pragma unroll
    for (int o = 16; o; o >>= 1) v += __shfl_xor_sync(0xffffffffu, v, o);
    int lane = threadIdx.x & 31, w = threadIdx.x >> 5;
    if (lane == 0) red[w] = v;
    __syncthreads();
    float r = (threadIdx.x < 8) ? red[threadIdx.x] : 0.0f;
    if (threadIdx.x < 32) {
        #pragma unroll
        for (int o = 4; o; o >>= 1) r += __shfl_xor_sync(0xffffffffu, r, o);
        if (threadIdx.x == 0) red[0] = r;
    }
    __syncthreads();
    float out = red[0];
    __syncthreads();
    return out;
}

// ---------------------------------------------------------------------------
// image fp32 -> hi/lo bf16 (elementwise).  Also zeroes g_vmean (blocks 0..7).
// ---------------------------------------------------------------------------
__global__ void conv_img(const float* __restrict__ img) {
    if (blockIdx.x < 8) g_vmean[blockIdx.x * 256 + threadIdx.x] = 0.0f;
    size_t i = ((size_t)blockIdx.x * 256 + threadIdx.x) * 4;
    float4 v = *(const float4*)(img + i);
    __nv_bfloat16 h[4], l[4];
    split2(v.x, h[0], l[0]); split2(v.y, h[1], l[1]);
    split2(v.z, h[2], l[2]); split2(v.w, h[3], l[3]);
    *(__nv_bfloat162*)(g_img_hi + i)     = __nv_bfloat162(h[0], h[1]);
    *(__nv_bfloat162*)(g_img_hi + i + 2) = __nv_bfloat162(h[2], h[3]);
    *(__nv_bfloat162*)(g_img_lo + i)     = __nv_bfloat162(l[0], l[1]);
    *(__nv_bfloat162*)(g_img_lo + i + 2) = __nv_bfloat162(l[2], l[3]);
}

// ---------------------------------------------------------------------------
// Wkv [K,N] fp32 -> W^T [N,K] hi/lo bf16 (tiled transpose)
// ---------------------------------------------------------------------------
__global__ void wtrans(const float* __restrict__ W,
                       __nv_bfloat16* __restrict__ Thi,
                       __nv_bfloat16* __restrict__ Tlo,
                       int Kd, int Nd) {
    __shared__ float t[32][33];
    int bx = blockIdx.x * 32;
    int by = blockIdx.y * 32;
    int x = threadIdx.x & 31, y4 = (threadIdx.x >> 5) * 4;
    #pragma unroll
    for (int i = 0; i < 4; i++)
        t[y4 + i][x] = W[(size_t)(by + y4 + i) * Nd + bx + x];
    __syncthreads();
    #pragma unroll
    for (int i = 0; i < 4; i++) {
        float v = t[x][y4 + i];
        __nv_bfloat16 h, l;
        split2(v, h, l);
        size_t o = (size_t)(bx + y4 + i) * Kd + by + x;
        Thi[o] = h;
        Tlo[o] = l;
    }
}

// ---------------------------------------------------------------------------
// bf16 split GEMM via mma.sync (HMMA), 4-stage cp.async pipeline,
// one barrier per ktile, REGISTER double-buffered fragments.
// CTA tile 128x256, 8 warps at 64x64.  K' = 3K split.
// v-half CTAs (col0 >= DIM) accumulate column sums into g_vmean (atomics).
// ---------------------------------------------------------------------------
#define GBM 128
#define GBN 256
#define GBK 64
#define KTILES 48
#define ABYTES (GBM * GBK * 2)                // 16384
#define BBYTES (GBN * GBK * 2)                // 32768
#define STG    4
#define SMEM_GEMM (STG * (ABYTES + BBYTES))   // 196608

__global__ __launch_bounds__(256, 1)
void gemm_hmma_split(const __nv_bfloat16* __restrict__ A_hi,
                     const __nv_bfloat16* __restrict__ A_lo,
                     const __nv_bfloat16* __restrict__ B_hi,
                     const __nv_bfloat16* __restrict__ B_lo,
                     float* __restrict__ C, int N) {
    extern __shared__ char smem[];
    const int K = 1024;
    uint32_t sb = smem_u32(smem);
    int tid = threadIdx.x;
    int lane = tid & 31, wid = tid >> 5;
    int row0 = blockIdx.y * GBM, col0 = blockIdx.x * GBN;

    int lr = tid >> 3;
    int lc = tid & 7;

    int wm = wid >> 2, wn = wid & 3;
    int m_warp = wm * 64, n_warp = wn * 64;
    int a_row = lane & 15;
    int a_colb = (lane >> 4) * 8;
    int b_row = (lane & 7) + 8 * ((lane >> 4) & 1);
    int b_colb = 8 * ((lane >> 3) & 1);

    float acc[4][8][4];
    #pragma unroll
    for (int i = 0; i < 4; i++)
        #pragma unroll
        for (int j = 0; j < 8; j++)
            #pragma unroll
            for (int q = 0; q < 4; q++) acc[i][j][q] = 0.0f;

    auto issue = [&](int kt) {
        int term = kt >> 4;
        int ks = (kt & 15) * GBK;
        uint32_t abase = sb + (uint32_t)((kt % STG) * (ABYTES + BBYTES));
        uint32_t bbase = abase + ABYTES;
        const __nv_bfloat16* Ag = (term < 2) ? A_hi : A_lo;
        const __nv_bfloat16* Bg = (term == 1) ? B_lo : B_hi;
        #pragma unroll
        for (int j = 0; j < 4; j++) {
            int r = lr + 32 * j;
            uint32_t off = (uint32_t)(r * 128 + lc * 16);
            cp_async16(abase + sw128(off),
                       Ag + (size_t)(row0 + r) * K + ks + lc * 8);
        }
        #pragma unroll
        for (int j = 0; j < 8; j++) {
            int r = lr + 32 * j;
            uint32_t off = (uint32_t)(r * 128 + lc * 16);
            cp_async16(bbase + sw128(off),
                       Bg + (size_t)(col0 + r) * K + ks + lc * 8);
        }
        asm volatile("cp.async.commit_group;" ::: "memory");
    };

    issue(0);
    issue(1);
    issue(2);

    #pragma unroll 1
    for (int kt = 0; kt < KTILES; kt++) {
        if (kt + 1 < KTILES) {
            asm volatile("cp.async.wait_group 2;" ::: "memory");
        } else {
            asm volatile("cp.async.wait_group 0;" ::: "memory");
        }
        __syncthreads();

        uint32_t ab = sb + (uint32_t)((kt % STG) * (ABYTES + BBYTES));
        uint32_t bb = ab + ABYTES;

        // register double-buffered fragments over the 4 k16 steps
        uint32_t a_r[2][4][4], b_r[2][4][4];
        auto load_frag = [&](int k16, int buf) {
            #pragma unroll
            for (int mf = 0; mf < 4; mf++) {
                uint32_t off = (uint32_t)((m_warp + mf * 16 + a_row) * 128 +
                                          (k16 * 16 + a_colb) * 2);
                ldsm4(a_r[buf][mf], ab + sw128(off));
            }
            #pragma unroll
            for (int nf2 = 0; nf2 < 4; nf2++) {
                uint32_t off = (uint32_t)((n_warp + nf2 * 16 + b_row) * 128 +
                                          (k16 * 16 + b_colb) * 2);
                ldsm4(b_r[buf][nf2], bb + sw128(off));
            }
        };

        load_frag(0, 0);
        #pragma unroll
        for (int k16 = 0; k16 < 4; k16++) {
            int cur = k16 & 1;
            if (k16 < 3) load_frag(k16 + 1, cur ^ 1);
            #pragma unroll
            for (int mf = 0; mf < 4; mf++)
                #pragma unroll
                for (int nf = 0; nf < 8; nf++) {
                    const uint32_t* b2 = &b_r[cur][nf >> 1][(nf & 1) * 2];
                    mma16816(acc[mf][nf], a_r[cur][mf], b2[0], b2[1]);
                }
        }

        if (kt + 3 < KTILES) issue(kt + 3);
    }

    // ---- epilogue: store C ----
    int r_base = row0 + m_warp + (lane >> 2);
    int c_base = col0 + n_warp + 2 * (lane & 3);
    #pragma unroll
    for (int mf = 0; mf < 4; mf++)
        #pragma unroll
        for (int nf = 0; nf < 8; nf++) {
            float* p = C + (size_t)(r_base + mf * 16) * N + c_base + nf * 8;
            *(float2*)p = make_float2(acc[mf][nf][0], acc[mf][nf][1]);
            *(float2*)(p + (size_t)8 * N) = make_float2(acc[mf][nf][2], acc[mf][nf][3]);
        }

    // ---- fused v column sums (only v half: col0 >= DIM) ----
    if (col0 >= DIM) {
        int b = row0 >> 10;
        #pragma unroll
        for (int nf = 0; nf < 8; nf++) {
            float c0s = 0.0f, c1s = 0.0f;
            #pragma unroll
            for (int mf = 0; mf < 4; mf++) {
                c0s += acc[mf][nf][0] + acc[mf][nf][2];
                c1s += acc[mf][nf][1] + acc[mf][nf][3];
            }
            #pragma unroll
            for (int o = 4; o <= 16; o <<= 1) {
                c0s += __shfl_xor_sync(0xffffffffu, c0s, o);
                c1s += __shfl_xor_sync(0xffffffffu, c1s, o);
            }
            if ((lane >> 2) == 0) {
                int c = c_base + nf * 8 - DIM;
                atomicAdd(&g_vmean[b * DIM + c], c0s);
                atomicAdd(&g_vmean[b * DIM + c + 1], c1s);
            }
        }
    }
}

// ---------------------------------------------------------------------------
// omean[b] = (vmean[b]/TM_TOT) @ Wo  — grid (16, BATCH)
// ---------------------------------------------------------------------------
__global__ __launch_bounds__(256)
void omean_kernel(const float* __restrict__ Wo) {
    __shared__ float x[DIM];
    __shared__ float part[8 * 64];
    int tid = threadIdx.x, lane = tid & 31, w = tid >> 5;
    int n0 = blockIdx.x * 64;
    int b = blockIdx.y;
    float4 v = ((const float4*)(g_vmean + b * DIM))[tid];
    const float sc = 1.0f / TM_TOT;
    x[4 * tid + 0] = v.x * sc; x[4 * tid + 1] = v.y * sc;
    x[4 * tid + 2] = v.z * sc; x[4 * tid + 3] = v.w * sc;
    __syncthreads();
    {
        float a0 = 0.0f, a1 = 0.0f;
        int n = n0 + lane * 2;
        const float* Wp = Wo + (size_t)(w * 128) * DIM + n;
        const float* xp = x + w * 128;
        #pragma unroll 8
        for (int kk = 0; kk < 128; kk++) {
            float xv = xp[kk];
            float2 wv = *(const float2*)(Wp + (size_t)kk * DIM);
            a0 = fmaf(xv, wv.x, a0);
            a1 = fmaf(xv, wv.y, a1);
        }
        part[w * 64 + lane * 2]     = a0;
        part[w * 64 + lane * 2 + 1] = a1;
    }
    __syncthreads();
    if (tid < 64) {
        float acc = 0.0f;
        #pragma unroll
        for (int ww = 0; ww < 8; ww++) acc += part[ww * 64 + tid];
        g_omean[b * DIM + n0 + tid] = acc;
    }
}

// ---------------------------------------------------------------------------
// Slot-batched fused LayerNorm + q GEMV.  grid (16 n-chunks, 4 slot-groups).
// ---------------------------------------------------------------------------
__global__ __launch_bounds__(256)
void qact_kernel(const float* __restrict__ text,
                 const float* __restrict__ gamma,
                 const float* __restrict__ beta,
                 const float* __restrict__ Wq) {
    __shared__ float xs[SB][DIM];      // 32 KB
    __shared__ float red[8];
    __shared__ float part[8 * 64];
    int tid = threadIdx.x, lane = tid & 31, w = tid >> 5;
    int n0 = blockIdx.x * 64;
    int nact = g_nact;

    for (int s0 = blockIdx.y * SB; s0 < nact; s0 += gridDim.y * SB) {
        int ns = min(SB, nact - s0);
        for (int si = 0; si < ns; si++) {
            int row = g_act[s0 + si];
            float4 v = ((const float4*)(text + (size_t)row * DIM))[tid];
            float sm = v.x + v.y + v.z + v.w;
            float mu = blockReduceSum256(sm, red) * (1.0f / DIM);
            float dx = v.x - mu, dy = v.y - mu, dz = v.z - mu, dw = v.w - mu;
            float var = blockReduceSum256(dx * dx + dy * dy + dz * dz + dw * dw, red)
                      * (1.0f / DIM);
            float inv = rsqrtf(var + EPS);
            float4 g = ((const float4*)gamma)[tid];
            float4 bt = ((const float4*)beta)[tid];
            xs[si][4 * tid + 0] = dx * inv * g.x + bt.x;
            xs[si][4 * tid + 1] = dy * inv * g.y + bt.y;
            xs[si][4 * tid + 2] = dz * inv * g.z + bt.z;
            xs[si][4 * tid + 3] = dw * inv * g.w + bt.w;
        }
        for (int si = ns; si < SB; si++) {
            xs[si][4 * tid + 0] = 0.f; xs[si][4 * tid + 1] = 0.f;
            xs[si][4 * tid + 2] = 0.f; xs[si][4 * tid + 3] = 0.f;
        }
        __syncthreads();

        float a0[SB], a1[SB];
        #pragma unroll
        for (int si = 0; si < SB; si++) { a0[si] = 0.f; a1[si] = 0.f; }
        int n = n0 + lane * 2;
        const float* Wp = Wq + (size_t)(w * 128) * DIM + n;
        #pragma unroll 4
        for (int kk = 0; kk < 128; kk++) {
            float2 wv = *(const float2*)(Wp + (size_t)kk * DIM);
            #pragma unroll
            for (int si = 0; si < SB; si++) {
                float xv = xs[si][w * 128 + kk];
                a0[si] = fmaf(xv, wv.x, a0[si]);
                a1[si] = fmaf(xv, wv.y, a1[si]);
            }
        }
        for (int si = 0; si < ns; si++) {
            part[w * 64 + lane * 2]     = a0[si];
            part[w * 64 + lane * 2 + 1] = a1[si];
            __syncthreads();
            if (tid < 64) {
                float acc = 0.0f;
                #pragma unroll
                for (int ww = 0; ww < 8; ww++) acc += part[ww * 64 + tid];
                g_qact[(size_t)(s0 + si) * DIM + n0 + tid] = acc;
            }
            __syncthreads();
        }
    }
}

// ---------------------------------------------------------------------------
// Segment attention per (slot, head-group of 2 heads). grid (64, 8).
// ---------------------------------------------------------------------------
__global__ __launch_bounds__(256)
void attn_act_kernel() {
    __shared__ float qs[128];
    __shared__ float S[2][M_MEDIA];
    __shared__ float part[8][128];
    int tid = threadIdx.x;
    int lane = tid & 31, w = tid >> 5;
    int hg = blockIdx.y;               // 0..7 (2 heads each)
    int nact = g_nact;

    for (int s = blockIdx.x; s < nact; s += gridDim.x) {
        int row = g_act[s];
        int b = row >> 11;
        int tt = g_tt[row];
        int j0 = (tt - 1) * M_MEDIA;

        if (tid < 128) qs[tid] = g_qact[(size_t)s * DIM + hg * 128 + tid];
        __syncthreads();

        int h = lane >> 4;
        int cc = (lane & 15) * 4;
        {
            const float scale = 0.125f;
            const float* qh = qs + h * 64 + cc;
            float q0 = qh[0], q1 = qh[1], q2 = qh[2], q3 = qh[3];
            const float* kbase = g_kv + ((size_t)(b * TM_TOT + j0 + w * 32)) * (2 * DIM)
                               + hg * 128 + h * 64 + cc;
            for (int jj = 0; jj < 32; jj++) {
                float4 k4 = *(const float4*)(kbase + (size_t)jj * (2 * DIM));
                float p = k4.x * q0 + k4.y * q1 + k4.z * q2 + k4.w * q3;
                p += __shfl_xor_sync(0xffffffffu, p, 8);
                p += __shfl_xor_sync(0xffffffffu, p, 4);
                p += __shfl_xor_sync(0xffffffffu, p, 2);
                p += __shfl_xor_sync(0xffffffffu, p, 1);
                if ((lane & 15) == 0) S[h][w * 32 + jj] = p * scale;
            }
        }
        __syncthreads();

        if (w < 2) {
            float vals[8];
            float m = -1e30f;
            #pragma unroll
            for (int k = 0; k < 8; k++) {
                vals[k] = S[w][lane + 32 * k];
                m = fmaxf(m, vals[k]);
            }
            #pragma unroll
            for (int o = 16; o; o >>= 1) m = fmaxf(m, __shfl_xor_sync(0xffffffffu, m, o));
            float sum = 0.0f;
            #pragma unroll
            for (int k = 0; k < 8; k++) { vals[k] = __expf(vals[k] - m); sum += vals[k]; }
            #pragma unroll
            for (int o = 16; o; o >>= 1) sum += __shfl_xor_sync(0xffffffffu, sum, o);
            float inv = 1.0f / sum;
            #pragma unroll
            for (int k = 0; k < 8; k++) S[w][lane + 32 * k] = vals[k] * inv;
        }
        __syncthreads();

        {
            float acc[4] = {0.f, 0.f, 0.f, 0.f};
            const float* vbase = g_kv + ((size_t)(b * TM_TOT + j0 + w * 32)) * (2 * DIM)
                               + DIM + hg * 128 + h * 64 + cc;
            #pragma unroll 4
            for (int jj = 0; jj < 32; jj++) {
                float p = S[h][w * 32 + jj];
                float4 v4 = *(const float4*)(vbase + (size_t)jj * (2 * DIM));
                acc[0] = fmaf(p, v4.x, acc[0]);
                acc[1] = fmaf(p, v4.y, acc[1]);
                acc[2] = fmaf(p, v4.z, acc[2]);
                acc[3] = fmaf(p, v4.w, acc[3]);
            }
            #pragma unroll
            for (int u = 0; u < 4; u++) part[w][h * 64 + cc + u] = acc[u];
        }
        __syncthreads();

        if (tid < 128) {
            float a = 0.0f;
            #pragma unroll
            for (int ww = 0; ww < 8; ww++) a += part[ww][tid];
            g_oact[(size_t)s * DIM + hg * 128 + tid] = a;
        }
        __syncthreads();
    }
}

// ---------------------------------------------------------------------------
// Fill output: tt==0 -> 0, tt>4 -> omean, active rows skipped
// ---------------------------------------------------------------------------
__global__ void fill_kernel(float* __restrict__ out) {
    int row = blockIdx.x;
    int tt = g_tt[row];
    if (tt >= 1 && tt <= T_MEDIA) return;
    int tid = threadIdx.x;
    int b = row >> 11;
    float4 val = (tt == 0) ? make_float4(0.f, 0.f, 0.f, 0.f)
                           : ((const float4*)(g_omean + b * DIM))[tid];
    ((float4*)(out + (size_t)row * DIM))[tid] = val;
}

// ---------------------------------------------------------------------------
// Slot-batched out GEMV: out[row] = oact[s] @ Wo.  grid (16, 8), SBO=4.
// ---------------------------------------------------------------------------
__global__ __launch_bounds__(256)
void out_act_kernel(const float* __restrict__ Wo, float* __restrict__ out) {
    __shared__ float xs[SBO][DIM];     // 16 KB
    __shared__ float part[8 * 64];
    int tid = threadIdx.x, lane = tid & 31, w = tid >> 5;
    int n0 = blockIdx.x * 64;
    int nact = g_nact;

    for (int s0 = blockIdx.y * SBO; s0 < nact; s0 += gridDim.y * SBO) {
        int ns = min(SBO, nact - s0);
        for (int si = 0; si < ns; si++)
            ((float4*)xs[si])[tid] = ((const float4*)(g_oact + (size_t)(s0 + si) * DIM))[tid];
        for (int si = ns; si < SBO; si++) {
            xs[si][4 * tid + 0] = 0.f; xs[si][4 * tid + 1] = 0.f;
            xs[si][4 * tid + 2] = 0.f; xs[si][4 * tid + 3] = 0.f;
        }
        __syncthreads();

        float a0[SBO], a1[SBO];
        #pragma unroll
        for (int si = 0; si < SBO; si++) { a0[si] = 0.f; a1[si] = 0.f; }
        int n = n0 + lane * 2;
        const float* Wp = Wo + (size_t)(w * 128) * DIM + n;
        #pragma unroll 4
        for (int kk = 0; kk < 128; kk++) {
            float2 wv = *(const float2*)(Wp + (size_t)kk * DIM);
            #pragma unroll
            for (int si = 0; si < SBO; si++) {
                float xv = xs[si][w * 128 + kk];
                a0[si] = fmaf(xv, wv.x, a0[si]);
                a1[si] = fmaf(xv, wv.y, a1[si]);
            }
        }
        for (int si = 0; si < ns; si++) {
            part[w * 64 + lane * 2]     = a0[si];
            part[w * 64 + lane * 2 + 1] = a1[si];
            __syncthreads();
            if (tid < 64) {
                float acc = 0.0f;
                #pragma unroll
                for (int ww = 0; ww < 8; ww++) acc += part[ww * 64 + tid];
                out[(size_t)g_act[s0 + si] * DIM + n0 + tid] = acc;
            }
            __syncthreads();
        }
    }
}

// ---------------------------------------------------------------------------
// Launch — two-stream fork/join.  s2: wtrans, scan+compact, qact, then
// (after GEMM event) omean + fill.  main: conv, GEMM, attn, out_act.
// ---------------------------------------------------------------------------
extern "C" void kernel_launch(void* const* d_in, const int* in_sizes, int n_in,
                              void* d_out, int out_size) {
    const float* text  = (const float*)d_in[0];
    const float* image = (const float*)d_in[1];
    const int*   loc   = (const int*)d_in[2];
    const float* Wq    = (const float*)d_in[3];
    const float* Wkv   = (const float*)d_in[4];
    const float* Wo    = (const float*)d_in[5];
    const float* gamma = (const float*)d_in[6];
    const float* beta  = (const float*)d_in[7];
    float* out = (float*)d_out;

    static cudaStream_t s2 = nullptr;
    static cudaEvent_t evFork = nullptr, evW = nullptr, evG = nullptr,
                       evJoin = nullptr, evFill = nullptr;
    static int inited = 0;
    if (!inited) {
        cudaFuncSetAttribute(gemm_hmma_split,
                             cudaFuncAttributeMaxDynamicSharedMemorySize, SMEM_GEMM);
        cudaStreamCreateWithFlags(&s2, cudaStreamNonBlocking);
        cudaEventCreateWithFlags(&evFork, cudaEventDisableTiming);
        cudaEventCreateWithFlags(&evW, cudaEventDisableTiming);
        cudaEventCreateWithFlags(&evG, cudaEventDisableTiming);
        cudaEventCreateWithFlags(&evJoin, cudaEventDisableTiming);
        cudaEventCreateWithFlags(&evFill, cudaEventDisableTiming);
        inited = 1;
    }

    __nv_bfloat16 *img_hi, *img_lo, *wkv_hi, *wkv_lo;
    float *p_kv;
    cudaGetSymbolAddress((void**)&img_hi, g_img_hi);
    cudaGetSymbolAddress((void**)&img_lo, g_img_lo);
    cudaGetSymbolAddress((void**)&wkv_hi, g_Wkv_hi);
    cudaGetSymbolAddress((void**)&wkv_lo, g_Wkv_lo);
    cudaGetSymbolAddress((void**)&p_kv,   g_kv);

    cudaEventRecord(evFork, 0);
    cudaStreamWaitEvent(s2, evFork, 0);

    // s2: wtrans (feeds GEMM)
    wtrans<<<dim3(2 * DIM / 32, DIM / 32), 256, 0, s2>>>(Wkv, wkv_hi, wkv_lo, DIM, 2 * DIM);
    cudaEventRecord(evW, s2);

    // main: conv (also zeroes vmean), then GEMM (needs wtrans)
    conv_img<<<(MKV * DIM) / (256 * 4), 256>>>(image);
    cudaStreamWaitEvent(0, evW, 0);
    gemm_hmma_split<<<dim3(2 * DIM / GBN, MKV / GBM), 256, SMEM_GEMM>>>(
        img_hi, img_lo, wkv_hi, wkv_lo, p_kv, 2 * DIM);
    cudaEventRecord(evG, 0);

    // s2: q-branch (overlaps GEMM), then omean+fill (overlap attn/out tail)
    scan_compact_kernel<<<1, 1024, 0, s2>>>(loc);
    qact_kernel<<<dim3(16, 4), 256, 0, s2>>>(text, gamma, beta, Wq);
    cudaEventRecord(evJoin, s2);
    cudaStreamWaitEvent(s2, evG, 0);
    omean_kernel<<<dim3(16, BATCH), 256, 0, s2>>>(Wo);
    fill_kernel<<<MQ, 256, 0, s2>>>(out);
    cudaEventRecord(evFill, s2);

    // main: join q-branch, then attention tail
    cudaStreamWaitEvent(0, evJoin, 0);
    attn_act_kernel<<<dim3(64, 8), 256>>>();
    out_act_kernel<<<dim3(16, 8), 256>>>(Wo, out);
    cudaStreamWaitEvent(0, evFill, 0);
}

// round 16
// speedup vs baseline: 1.2148x; 1.2148x over previous
#include <cuda_runtime.h>
#include <cuda_fp16.h>
#include <math.h>
#include <stdint.h>

// Problem constants
#define BATCH   2
#define NTXT    2048
#define T_MEDIA 4
#define M_MEDIA 256
#define TM_TOT  1024
#define DIM     1024
#define HEADS   16
#define DH      64
#define EPS     1e-5f

#define MQ  (BATCH * NTXT)     // 4096
#define MKV (BATCH * TM_TOT)   // 2048
#define SB  8                  // slots batched in qact
#define SBO 4                  // slots batched in out_act

// ---------------------------------------------------------------------------
// Scratch (device globals; no allocations allowed)
// ---------------------------------------------------------------------------
__device__ __half g_img_hi[MKV * DIM];
__device__ __half g_img_lo[MKV * DIM];
__device__ __half g_Wkv_h [2 * DIM * DIM];         // W^T [N,K] fp16 hi

__device__ float g_kv    [MKV * 2 * DIM];          // k | v (fp32)
__device__ float g_impart[BATCH * 32 * DIM];       // image partial col sums
__device__ float g_vmean [BATCH * DIM];            // mean(img) @ Wv  (fp32 exact)
__device__ float g_omean [BATCH * DIM];            // vmean @ Wo      (fp32 exact)
__device__ int   g_tt    [MQ];                     // txt_time
__device__ int   g_act   [MQ];                     // active rows (tt in [1..4])
__device__ int   g_nact;
__device__ float g_qact  [MQ * DIM];               // q rows for active queries
__device__ float g_oact  [MQ * DIM];               // attention out for active queries

// ---------------------------------------------------------------------------
// PTX helpers (sm_80-baseline only; NO tcgen05 — ptxas target lacks 'a')
// ---------------------------------------------------------------------------
__device__ __forceinline__ uint32_t smem_u32(const void* p) {
    uint32_t a;
    asm("{ .reg .u64 t; cvta.to.shared.u64 t, %1; cvt.u32.u64 %0, t; }" : "=r"(a) : "l"(p));
    return a;
}
__device__ __forceinline__ void cp_async16(uint32_t dst, const void* src) {
    asm volatile("cp.async.cg.shared.global [%0], [%1], 16;\n" :: "r"(dst), "l"(src));
}
__device__ __forceinline__ void ldsm4(uint32_t* r, uint32_t addr) {
    asm volatile("ldmatrix.sync.aligned.m8n8.x4.shared.b16 {%0,%1,%2,%3}, [%4];"
                 : "=r"(r[0]), "=r"(r[1]), "=r"(r[2]), "=r"(r[3]) : "r"(addr));
}
__device__ __forceinline__ void mma16816h(float* c, const uint32_t* a,
                                          uint32_t b0, uint32_t b1) {
    asm volatile(
        "mma.sync.aligned.m16n8k16.row.col.f32.f16.f16.f32 "
        "{%0,%1,%2,%3}, {%4,%5,%6,%7}, {%8,%9}, {%0,%1,%2,%3};"
        : "+f"(c[0]), "+f"(c[1]), "+f"(c[2]), "+f"(c[3])
        : "r"(a[0]), "r"(a[1]), "r"(a[2]), "r"(a[3]), "r"(b0), "r"(b1));
}
__device__ __forceinline__ uint32_t sw128(uint32_t off) {
    return off ^ ((off >> 3) & 0x70);
}
__device__ __forceinline__ void split2h(float v, __half& h, __half& l) {
    h = __float2half_rn(v);
    l = __float2half_rn(v - __half2float(h));
}

// ---------------------------------------------------------------------------
// Scan + compact fused: one block of 1024 threads handles both batches.
// ---------------------------------------------------------------------------
__global__ void scan_compact_kernel(const int* __restrict__ loc) {
    __shared__ int s[1024];
    int tid = threadIdx.x;
    if (tid == 0) g_nact = 0;
    __syncthreads();
    for (int b = 0; b < BATCH; b++) {
        const int* L = loc + b * NTXT;
        int a0 = L[2 * tid];
        int a1 = L[2 * tid + 1];
        int v0 = a0, v1 = a0 + a1;
        s[tid] = v1;
        __syncthreads();
        for (int off = 1; off < 1024; off <<= 1) {
            int t = (tid >= off) ? s[tid - off] : 0;
            __syncthreads();
            s[tid] += t;
            __syncthreads();
        }
        int excl = s[tid] - v1;
        int t0 = excl + v0, t1 = excl + v1;
        int r0 = b * NTXT + 2 * tid, r1 = r0 + 1;
        g_tt[r0] = t0;
        g_tt[r1] = t1;
        if (t0 >= 1 && t0 <= T_MEDIA) g_act[atomicAdd(&g_nact, 1)] = r0;
        if (t1 >= 1 && t1 <= T_MEDIA) g_act[atomicAdd(&g_nact, 1)] = r1;
        __syncthreads();
    }
}

// ---------------------------------------------------------------------------
// Block reduce helper (256 threads)
// ---------------------------------------------------------------------------
__device__ __forceinline__ float blockReduceSum256(float v, float* red) {
    #pragma unroll
    for (int o = 16; o; o >>= 1) v += __shfl_xor_sync(0xffffffffu, v, o);
    int lane = threadIdx.x & 31, w = threadIdx.x >> 5;
    if (lane == 0) red[w] = v;
    __syncthreads();
    float r = (threadIdx.x < 8) ? red[threadIdx.x] : 0.0f;
    if (threadIdx.x < 32) {
        #pragma unroll
        for (int o = 4; o; o >>= 1) r += __shfl_xor_sync(0xffffffffu, r, o);
        if (threadIdx.x == 0) red[0] = r;
    }
    __syncthreads();
    float out = red[0];
    __syncthreads();
    return out;
}

// ---------------------------------------------------------------------------
// image fp32 -> hi/lo fp16 (elementwise)
// ---------------------------------------------------------------------------
__global__ void conv_img(const float* __restrict__ img) {
    size_t i = ((size_t)blockIdx.x * 256 + threadIdx.x) * 4;
    float4 v = *(const float4*)(img + i);
    __half h[4], l[4];
    split2h(v.x, h[0], l[0]); split2h(v.y, h[1], l[1]);
    split2h(v.z, h[2], l[2]); split2h(v.w, h[3], l[3]);
    *(__half2*)(g_img_hi + i)     = __halves2half2(h[0], h[1]);
    *(__half2*)(g_img_hi + i + 2) = __halves2half2(h[2], h[3]);
    *(__half2*)(g_img_lo + i)     = __halves2half2(l[0], l[1]);
    *(__half2*)(g_img_lo + i + 2) = __halves2half2(l[2], l[3]);
}

// ---------------------------------------------------------------------------
// Wkv [K,N] fp32 -> W^T [N,K] fp16 (tiled transpose, hi only)
// ---------------------------------------------------------------------------
__global__ void wtrans(const float* __restrict__ W,
                       __half* __restrict__ Th,
                       int Kd, int Nd) {
    __shared__ float t[32][33];
    int bx = blockIdx.x * 32;
    int by = blockIdx.y * 32;
    int x = threadIdx.x & 31, y4 = (threadIdx.x >> 5) * 4;
    #pragma unroll
    for (int i = 0; i < 4; i++)
        t[y4 + i][x] = W[(size_t)(by + y4 + i) * Nd + bx + x];
    __syncthreads();
    #pragma unroll
    for (int i = 0; i < 4; i++) {
        size_t o = (size_t)(bx + y4 + i) * Kd + by + x;
        Th[o] = __float2half_rn(t[x][y4 + i]);
    }
}

// ---------------------------------------------------------------------------
// fp16 2-term split GEMM via mma.sync (HMMA), 4-stage cp.async pipeline,
// one barrier per ktile (R14-proven inner loop).
// C = (A_hi + A_lo) @ B_hi^T ; K' = 2K (KTILES = 32).
// CTA tile 128x256, 8 warps at 64x64.
// ---------------------------------------------------------------------------
#define GBM 128
#define GBN 256
#define GBK 64
#define KTILES 32
#define ABYTES (GBM * GBK * 2)                // 16384
#define BBYTES (GBN * GBK * 2)                // 32768
#define STG    4
#define SMEM_GEMM (STG * (ABYTES + BBYTES))   // 196608

__global__ __launch_bounds__(256, 1)
void gemm_hmma_split(const __half* __restrict__ A_hi,
                     const __half* __restrict__ A_lo,
                     const __half* __restrict__ B_hi,
                     float* __restrict__ C, int N) {
    extern __shared__ char smem[];
    const int K = 1024;
    uint32_t sb = smem_u32(smem);
    int tid = threadIdx.x;
    int lane = tid & 31, wid = tid >> 5;
    int row0 = blockIdx.y * GBM, col0 = blockIdx.x * GBN;

    int lr = tid >> 3;
    int lc = tid & 7;

    int wm = wid >> 2, wn = wid & 3;
    int m_warp = wm * 64, n_warp = wn * 64;
    int a_row = lane & 15;
    int a_colb = (lane >> 4) * 8;
    int b_row = (lane & 7) + 8 * ((lane >> 4) & 1);
    int b_colb = 8 * ((lane >> 3) & 1);

    float acc[4][8][4];
    #pragma unroll
    for (int i = 0; i < 4; i++)
        #pragma unroll
        for (int j = 0; j < 8; j++)
            #pragma unroll
            for (int q = 0; q < 4; q++) acc[i][j][q] = 0.0f;

    auto issue = [&](int kt) {
        int term = kt >> 4;                 // 0: A_hi, 1: A_lo
        int ks = (kt & 15) * GBK;
        uint32_t abase = sb + (uint32_t)((kt % STG) * (ABYTES + BBYTES));
        uint32_t bbase = abase + ABYTES;
        const __half* Ag = (term == 0) ? A_hi : A_lo;
        #pragma unroll
        for (int j = 0; j < 4; j++) {
            int r = lr + 32 * j;
            uint32_t off = (uint32_t)(r * 128 + lc * 16);
            cp_async16(abase + sw128(off),
                       Ag + (size_t)(row0 + r) * K + ks + lc * 8);
        }
        #pragma unroll
        for (int j = 0; j < 8; j++) {
            int r = lr + 32 * j;
            uint32_t off = (uint32_t)(r * 128 + lc * 16);
            cp_async16(bbase + sw128(off),
                       B_hi + (size_t)(col0 + r) * K + ks + lc * 8);
        }
        asm volatile("cp.async.commit_group;" ::: "memory");
    };

    issue(0);
    issue(1);
    issue(2);

    #pragma unroll 1
    for (int kt = 0; kt < KTILES; kt++) {
        if (kt + 1 < KTILES) {
            asm volatile("cp.async.wait_group 2;" ::: "memory");
        } else {
            asm volatile("cp.async.wait_group 0;" ::: "memory");
        }
        __syncthreads();

        uint32_t ab = sb + (uint32_t)((kt % STG) * (ABYTES + BBYTES));
        uint32_t bb = ab + ABYTES;
        #pragma unroll
        for (int k16 = 0; k16 < 4; k16++) {
            uint32_t a_r[4][4], b_r[4][4];
            #pragma unroll
            for (int mf = 0; mf < 4; mf++) {
                uint32_t off = (uint32_t)((m_warp + mf * 16 + a_row) * 128 +
                                          (k16 * 16 + a_colb) * 2);
                ldsm4(a_r[mf], ab + sw128(off));
            }
            #pragma unroll
            for (int nf2 = 0; nf2 < 4; nf2++) {
                uint32_t off = (uint32_t)((n_warp + nf2 * 16 + b_row) * 128 +
                                          (k16 * 16 + b_colb) * 2);
                ldsm4(b_r[nf2], bb + sw128(off));
            }
            #pragma unroll
            for (int mf = 0; mf < 4; mf++)
                #pragma unroll
                for (int nf = 0; nf < 8; nf++) {
                    const uint32_t* b2 = &b_r[nf >> 1][(nf & 1) * 2];
                    mma16816h(acc[mf][nf], a_r[mf], b2[0], b2[1]);
                }
        }

        if (kt + 3 < KTILES) issue(kt + 3);
    }

    // ---- epilogue: store C ----
    int r_base = row0 + m_warp + (lane >> 2);
    int c_base = col0 + n_warp + 2 * (lane & 3);
    #pragma unroll
    for (int mf = 0; mf < 4; mf++)
        #pragma unroll
        for (int nf = 0; nf < 8; nf++) {
            float* p = C + (size_t)(r_base + mf * 16) * N + c_base + nf * 8;
            *(float2*)p = make_float2(acc[mf][nf][0], acc[mf][nf][1]);
            *(float2*)(p + (size_t)8 * N) = make_float2(acc[mf][nf][2], acc[mf][nf][3]);
        }
}

// ---------------------------------------------------------------------------
// image column partial sums + mean (exact fp32 vmean path)
// ---------------------------------------------------------------------------
__global__ void imgmean_part(const float* __restrict__ image) {
    int c  = blockIdx.x * 256 + threadIdx.x;
    int ry = blockIdx.y;                    // 0..31
    int b  = blockIdx.z;
    const float* base = image + ((size_t)(b * TM_TOT + ry * 32)) * DIM + c;
    float s = 0.0f;
    #pragma unroll 8
    for (int j = 0; j < 32; j++) s += base[(size_t)j * DIM];
    g_impart[(b * 32 + ry) * DIM + c] = s;
}

__global__ void imgmean_final() {
    int c = blockIdx.x * 256 + threadIdx.x;
    int b = blockIdx.y;
    float s = 0.0f;
    #pragma unroll
    for (int r = 0; r < 32; r++) s += g_impart[(b * 32 + r) * DIM + c];
    g_impart[b * 32 * DIM + c] = s * (1.0f / TM_TOT);   // row 0 holds imgmean
}

// vmean[b] = imgmean[b] @ Wv  (Wv = Wkv cols [1024,2048), ldw 2048) — exact
__global__ __launch_bounds__(256)
void vmean_kernel(const float* __restrict__ Wkv) {
    __shared__ float x[DIM];
    __shared__ float part[8 * 64];
    int tid = threadIdx.x, lane = tid & 31, w = tid >> 5;
    int n0 = blockIdx.x * 64;
    int b = blockIdx.y;
    ((float4*)x)[tid] = ((const float4*)(g_impart + b * 32 * DIM))[tid];
    __syncthreads();
    {
        float a0 = 0.0f, a1 = 0.0f;
        int n = n0 + lane * 2;
        const float* Wp = Wkv + (size_t)(w * 128) * (2 * DIM) + DIM + n;
        const float* xp = x + w * 128;
        #pragma unroll 8
        for (int kk = 0; kk < 128; kk++) {
            float xv = xp[kk];
            float2 wv = *(const float2*)(Wp + (size_t)kk * (2 * DIM));
            a0 = fmaf(xv, wv.x, a0);
            a1 = fmaf(xv, wv.y, a1);
        }
        part[w * 64 + lane * 2]     = a0;
        part[w * 64 + lane * 2 + 1] = a1;
    }
    __syncthreads();
    if (tid < 64) {
        float acc = 0.0f;
        #pragma unroll
        for (int ww = 0; ww < 8; ww++) acc += part[ww * 64 + tid];
        g_vmean[b * DIM + n0 + tid] = acc;
    }
}

// omean[b] = vmean[b] @ Wo — exact
__global__ __launch_bounds__(256)
void omean_kernel(const float* __restrict__ Wo) {
    __shared__ float x[DIM];
    __shared__ float part[8 * 64];
    int tid = threadIdx.x, lane = tid & 31, w = tid >> 5;
    int n0 = blockIdx.x * 64;
    int b = blockIdx.y;
    ((float4*)x)[tid] = ((const float4*)(g_vmean + b * DIM))[tid];
    __syncthreads();
    {
        float a0 = 0.0f, a1 = 0.0f;
        int n = n0 + lane * 2;
        const float* Wp = Wo + (size_t)(w * 128) * DIM + n;
        const float* xp = x + w * 128;
        #pragma unroll 8
        for (int kk = 0; kk < 128; kk++) {
            float xv = xp[kk];
            float2 wv = *(const float2*)(Wp + (size_t)kk * DIM);
            a0 = fmaf(xv, wv.x, a0);
            a1 = fmaf(xv, wv.y, a1);
        }
        part[w * 64 + lane * 2]     = a0;
        part[w * 64 + lane * 2 + 1] = a1;
    }
    __syncthreads();
    if (tid < 64) {
        float acc = 0.0f;
        #pragma unroll
        for (int ww = 0; ww < 8; ww++) acc += part[ww * 64 + tid];
        g_omean[b * DIM + n0 + tid] = acc;
    }
}

// ---------------------------------------------------------------------------
// Slot-batched fused LayerNorm + q GEMV.  grid (16 n-chunks, 4 slot-groups).
// ---------------------------------------------------------------------------
__global__ __launch_bounds__(256)
void qact_kernel(const float* __restrict__ text,
                 const float* __restrict__ gamma,
                 const float* __restrict__ beta,
                 const float* __restrict__ Wq) {
    __shared__ float xs[SB][DIM];      // 32 KB
    __shared__ float red[8];
    __shared__ float part[8 * 64];
    int tid = threadIdx.x, lane = tid & 31, w = tid >> 5;
    int n0 = blockIdx.x * 64;
    int nact = g_nact;

    for (int s0 = blockIdx.y * SB; s0 < nact; s0 += gridDim.y * SB) {
        int ns = min(SB, nact - s0);
        for (int si = 0; si < ns; si++) {
            int row = g_act[s0 + si];
            float4 v = ((const float4*)(text + (size_t)row * DIM))[tid];
            float sm = v.x + v.y + v.z + v.w;
            float mu = blockReduceSum256(sm, red) * (1.0f / DIM);
            float dx = v.x - mu, dy = v.y - mu, dz = v.z - mu, dw = v.w - mu;
            float var = blockReduceSum256(dx * dx + dy * dy + dz * dz + dw * dw, red)
                      * (1.0f / DIM);
            float inv = rsqrtf(var + EPS);
            float4 g = ((const float4*)gamma)[tid];
            float4 bt = ((const float4*)beta)[tid];
            xs[si][4 * tid + 0] = dx * inv * g.x + bt.x;
            xs[si][4 * tid + 1] = dy * inv * g.y + bt.y;
            xs[si][4 * tid + 2] = dz * inv * g.z + bt.z;
            xs[si][4 * tid + 3] = dw * inv * g.w + bt.w;
        }
        for (int si = ns; si < SB; si++) {
            xs[si][4 * tid + 0] = 0.f; xs[si][4 * tid + 1] = 0.f;
            xs[si][4 * tid + 2] = 0.f; xs[si][4 * tid + 3] = 0.f;
        }
        __syncthreads();

        float a0[SB], a1[SB];
        #pragma unroll
        for (int si = 0; si < SB; si++) { a0[si] = 0.f; a1[si] = 0.f; }
        int n = n0 + lane * 2;
        const float* Wp = Wq + (size_t)(w * 128) * DIM + n;
        #pragma unroll 4
        for (int kk = 0; kk < 128; kk++) {
            float2 wv = *(const float2*)(Wp + (size_t)kk * DIM);
            #pragma unroll
            for (int si = 0; si < SB; si++) {
                float xv = xs[si][w * 128 + kk];
                a0[si] = fmaf(xv, wv.x, a0[si]);
                a1[si] = fmaf(xv, wv.y, a1[si]);
            }
        }
        for (int si = 0; si < ns; si++) {
            part[w * 64 + lane * 2]     = a0[si];
            part[w * 64 + lane * 2 + 1] = a1[si];
            __syncthreads();
            if (tid < 64) {
                float acc = 0.0f;
                #pragma unroll
                for (int ww = 0; ww < 8; ww++) acc += part[ww * 64 + tid];
                g_qact[(size_t)(s0 + si) * DIM + n0 + tid] = acc;
            }
            __syncthreads();
        }
    }
}

// ---------------------------------------------------------------------------
// Segment attention per (slot, head-group of 2 heads). grid (64, 8).
// ---------------------------------------------------------------------------
__global__ __launch_bounds__(256)
void attn_act_kernel() {
    __shared__ float qs[128];
    __shared__ float S[2][M_MEDIA];
    __shared__ float part[8][128];
    int tid = threadIdx.x;
    int lane = tid & 31, w = tid >> 5;
    int hg = blockIdx.y;               // 0..7 (2 heads each)
    int nact = g_nact;

    for (int s = blockIdx.x; s < nact; s += gridDim.x) {
        int row = g_act[s];
        int b = row >> 11;
        int tt = g_tt[row];
        int j0 = (tt - 1) * M_MEDIA;

        if (tid < 128) qs[tid] = g_qact[(size_t)s * DIM + hg * 128 + tid];
        __syncthreads();

        int h = lane >> 4;
        int cc = (lane & 15) * 4;
        {
            const float scale = 0.125f;
            const float* qh = qs + h * 64 + cc;
            float q0 = qh[0], q1 = qh[1], q2 = qh[2], q3 = qh[3];
            const float* kbase = g_kv + ((size_t)(b * TM_TOT + j0 + w * 32)) * (2 * DIM)
                               + hg * 128 + h * 64 + cc;
            for (int jj = 0; jj < 32; jj++) {
                float4 k4 = *(const float4*)(kbase + (size_t)jj * (2 * DIM));
                float p = k4.x * q0 + k4.y * q1 + k4.z * q2 + k4.w * q3;
                p += __shfl_xor_sync(0xffffffffu, p, 8);
                p += __shfl_xor_sync(0xffffffffu, p, 4);
                p += __shfl_xor_sync(0xffffffffu, p, 2);
                p += __shfl_xor_sync(0xffffffffu, p, 1);
                if ((lane & 15) == 0) S[h][w * 32 + jj] = p * scale;
            }
        }
        __syncthreads();

        if (w < 2) {
            float vals[8];
            float m = -1e30f;
            #pragma unroll
            for (int k = 0; k < 8; k++) {
                vals[k] = S[w][lane + 32 * k];
                m = fmaxf(m, vals[k]);
            }
            #pragma unroll
            for (int o = 16; o; o >>= 1) m = fmaxf(m, __shfl_xor_sync(0xffffffffu, m, o));
            float sum = 0.0f;
            #pragma unroll
            for (int k = 0; k < 8; k++) { vals[k] = __expf(vals[k] - m); sum += vals[k]; }
            #pragma unroll
            for (int o = 16; o; o >>= 1) sum += __shfl_xor_sync(0xffffffffu, sum, o);
            float inv = 1.0f / sum;
            #pragma unroll
            for (int k = 0; k < 8; k++) S[w][lane + 32 * k] = vals[k] * inv;
        }
        __syncthreads();

        {
            float acc[4] = {0.f, 0.f, 0.f, 0.f};
            const float* vbase = g_kv + ((size_t)(b * TM_TOT + j0 + w * 32)) * (2 * DIM)
                               + DIM + hg * 128 + h * 64 + cc;
            #pragma unroll 4
            for (int jj = 0; jj < 32; jj++) {
                float p = S[h][w * 32 + jj];
                float4 v4 = *(const float4*)(vbase + (size_t)jj * (2 * DIM));
                acc[0] = fmaf(p, v4.x, acc[0]);
                acc[1] = fmaf(p, v4.y, acc[1]);
                acc[2] = fmaf(p, v4.z, acc[2]);
                acc[3] = fmaf(p, v4.w, acc[3]);
            }
            #pragma unroll
            for (int u = 0; u < 4; u++) part[w][h * 64 + cc + u] = acc[u];
        }
        __syncthreads();

        if (tid < 128) {
            float a = 0.0f;
            #pragma unroll
            for (int ww = 0; ww < 8; ww++) a += part[ww][tid];
            g_oact[(size_t)s * DIM + hg * 128 + tid] = a;
        }
        __syncthreads();
    }
}

// ---------------------------------------------------------------------------
// Fill output: tt==0 -> 0, tt>4 -> omean, active rows skipped
// ---------------------------------------------------------------------------
__global__ void fill_kernel(float* __restrict__ out) {
    int row = blockIdx.x;
    int tt = g_tt[row];
    if (tt >= 1 && tt <= T_MEDIA) return;
    int tid = threadIdx.x;
    int b = row >> 11;
    float4 val = (tt == 0) ? make_float4(0.f, 0.f, 0.f, 0.f)
                           : ((const float4*)(g_omean + b * DIM))[tid];
    ((float4*)(out + (size_t)row * DIM))[tid] = val;
}

// ---------------------------------------------------------------------------
// Slot-batched out GEMV: out[row] = oact[s] @ Wo.  grid (16, 8), SBO=4.
// ---------------------------------------------------------------------------
__global__ __launch_bounds__(256)
void out_act_kernel(const float* __restrict__ Wo, float* __restrict__ out) {
    __shared__ float xs[SBO][DIM];     // 16 KB
    __shared__ float part[8 * 64];
    int tid = threadIdx.x, lane = tid & 31, w = tid >> 5;
    int n0 = blockIdx.x * 64;
    int nact = g_nact;

    for (int s0 = blockIdx.y * SBO; s0 < nact; s0 += gridDim.y * SBO) {
        int ns = min(SBO, nact - s0);
        for (int si = 0; si < ns; si++)
            ((float4*)xs[si])[tid] = ((const float4*)(g_oact + (size_t)(s0 + si) * DIM))[tid];
        for (int si = ns; si < SBO; si++) {
            xs[si][4 * tid + 0] = 0.f; xs[si][4 * tid + 1] = 0.f;
            xs[si][4 * tid + 2] = 0.f; xs[si][4 * tid + 3] = 0.f;
        }
        __syncthreads();

        float a0[SBO], a1[SBO];
        #pragma unroll
        for (int si = 0; si < SBO; si++) { a0[si] = 0.f; a1[si] = 0.f; }
        int n = n0 + lane * 2;
        const float* Wp = Wo + (size_t)(w * 128) * DIM + n;
        #pragma unroll 4
        for (int kk = 0; kk < 128; kk++) {
            float2 wv = *(const float2*)(Wp + (size_t)kk * DIM);
            #pragma unroll
            for (int si = 0; si < SBO; si++) {
                float xv = xs[si][w * 128 + kk];
                a0[si] = fmaf(xv, wv.x, a0[si]);
                a1[si] = fmaf(xv, wv.y, a1[si]);
            }
        }
        for (int si = 0; si < ns; si++) {
            part[w * 64 + lane * 2]     = a0[si];
            part[w * 64 + lane * 2 + 1] = a1[si];
            __syncthreads();
            if (tid < 64) {
                float acc = 0.0f;
                #pragma unroll
                for (int ww = 0; ww < 8; ww++) acc += part[ww * 64 + tid];
                out[(size_t)g_act[s0 + si] * DIM + n0 + tid] = acc;
            }
            __syncthreads();
        }
    }
}

// ---------------------------------------------------------------------------
// Launch — two streams.
// main: conv -> GEMM -> attn -> out_act
// s2:   wtrans(evW) -> scan -> qact(evJoin) -> imgmean chain -> omean -> fill
// The omean/fill chain is GEMM-independent and overlaps the attn/out tail.
// ---------------------------------------------------------------------------
extern "C" void kernel_launch(void* const* d_in, const int* in_sizes, int n_in,
                              void* d_out, int out_size) {
    const float* text  = (const float*)d_in[0];
    const float* image = (const float*)d_in[1];
    const int*   loc   = (const int*)d_in[2];
    const float* Wq    = (const float*)d_in[3];
    const float* Wkv   = (const float*)d_in[4];
    const float* Wo    = (const float*)d_in[5];
    const float* gamma = (const float*)d_in[6];
    const float* beta  = (const float*)d_in[7];
    float* out = (float*)d_out;

    static cudaStream_t s2 = nullptr;
    static cudaEvent_t evFork = nullptr, evW = nullptr, evJoin = nullptr, evFill = nullptr;
    static int inited = 0;
    if (!inited) {
        cudaFuncSetAttribute(gemm_hmma_split,
                             cudaFuncAttributeMaxDynamicSharedMemorySize, SMEM_GEMM);
        cudaStreamCreateWithFlags(&s2, cudaStreamNonBlocking);
        cudaEventCreateWithFlags(&evFork, cudaEventDisableTiming);
        cudaEventCreateWithFlags(&evW, cudaEventDisableTiming);
        cudaEventCreateWithFlags(&evJoin, cudaEventDisableTiming);
        cudaEventCreateWithFlags(&evFill, cudaEventDisableTiming);
        inited = 1;
    }

    __half *img_hi, *img_lo, *wkv_h;
    float *p_kv;
    cudaGetSymbolAddress((void**)&img_hi, g_img_hi);
    cudaGetSymbolAddress((void**)&img_lo, g_img_lo);
    cudaGetSymbolAddress((void**)&wkv_h,  g_Wkv_h);
    cudaGetSymbolAddress((void**)&p_kv,   g_kv);

    cudaEventRecord(evFork, 0);
    cudaStreamWaitEvent(s2, evFork, 0);

    // s2: wtrans (feeds GEMM)
    wtrans<<<dim3(2 * DIM / 32, DIM / 32), 256, 0, s2>>>(Wkv, wkv_h, DIM, 2 * DIM);
    cudaEventRecord(evW, s2);

    // main: conv, then GEMM (needs wtrans)
    conv_img<<<(MKV * DIM) / (256 * 4), 256>>>(image);
    cudaStreamWaitEvent(0, evW, 0);
    gemm_hmma_split<<<dim3(2 * DIM / GBN, MKV / GBM), 256, SMEM_GEMM>>>(
        img_hi, img_lo, wkv_h, p_kv, 2 * DIM);

    // s2: q-branch (overlaps GEMM), then the exact mean chain + fill
    scan_compact_kernel<<<1, 1024, 0, s2>>>(loc);
    qact_kernel<<<dim3(16, 4), 256, 0, s2>>>(text, gamma, beta, Wq);
    cudaEventRecord(evJoin, s2);
    imgmean_part<<<dim3(DIM / 256, 32, BATCH), 256, 0, s2>>>(image);
    imgmean_final<<<dim3(DIM / 256, BATCH), 256, 0, s2>>>();
    vmean_kernel<<<dim3(16, BATCH), 256, 0, s2>>>(Wkv);
    omean_kernel<<<dim3(16, BATCH), 256, 0, s2>>>(Wo);
    fill_kernel<<<MQ, 256, 0, s2>>>(out);
    cudaEventRecord(evFill, s2);

    // main: join q-branch, then attention tail
    cudaStreamWaitEvent(0, evJoin, 0);
    attn_act_kernel<<<dim3(64, 8), 256>>>();
    out_act_kernel<<<dim3(16, 8), 256>>>(Wo, out);
    cudaStreamWaitEvent(0, evFill, 0);
}

// round 17
// speedup vs baseline: 1.3695x; 1.1273x over previous
#include <cuda_runtime.h>
#include <cuda_fp16.h>
#include <math.h>
#include <stdint.h>

// Problem constants
#define BATCH   2
#define NTXT    2048
#define T_MEDIA 4
#define M_MEDIA 256
#define TM_TOT  1024
#define DIM     1024
#define HEADS   16
#define DH      64
#define EPS     1e-5f

#define MQ  (BATCH * NTXT)     // 4096
#define MKV (BATCH * TM_TOT)   // 2048
#define SB  4                  // slots batched in qact
#define SBO 4                  // slots batched in out_act

// ---------------------------------------------------------------------------
// Scratch (device globals; no allocations allowed)
// ---------------------------------------------------------------------------
__device__ __half g_img_h[MKV * DIM];
__device__ __half g_Wkv_h[2 * DIM * DIM];          // W^T [N,K] fp16

__device__ float g_kv    [MKV * 2 * DIM];          // k | v (fp32 acc)
__device__ float g_impart[BATCH * 32 * DIM];       // image partial col sums
__device__ float g_vmean [BATCH * DIM];            // mean(img) @ Wv  (fp32 exact)
__device__ float g_omean [BATCH * DIM];            // vmean @ Wo      (fp32 exact)
__device__ int   g_tt    [MQ];                     // txt_time
__device__ int   g_act   [MQ];                     // active rows (tt in [1..4])
__device__ int   g_nact;
__device__ float g_qact  [MQ * DIM];               // q rows for active queries
__device__ float g_oact  [MQ * DIM];               // attention out for active queries

// ---------------------------------------------------------------------------
// PTX helpers (sm_80-baseline only; NO tcgen05 — ptxas target lacks 'a')
// ---------------------------------------------------------------------------
__device__ __forceinline__ uint32_t smem_u32(const void* p) {
    uint32_t a;
    asm("{ .reg .u64 t; cvta.to.shared.u64 t, %1; cvt.u32.u64 %0, t; }" : "=r"(a) : "l"(p));
    return a;
}
__device__ __forceinline__ void cp_async16(uint32_t dst, const void* src) {
    asm volatile("cp.async.cg.shared.global [%0], [%1], 16;\n" :: "r"(dst), "l"(src));
}
__device__ __forceinline__ void ldsm4(uint32_t* r, uint32_t addr) {
    asm volatile("ldmatrix.sync.aligned.m8n8.x4.shared.b16 {%0,%1,%2,%3}, [%4];"
                 : "=r"(r[0]), "=r"(r[1]), "=r"(r[2]), "=r"(r[3]) : "r"(addr));
}
__device__ __forceinline__ void mma16816h(float* c, const uint32_t* a,
                                          uint32_t b0, uint32_t b1) {
    asm volatile(
        "mma.sync.aligned.m16n8k16.row.col.f32.f16.f16.f32 "
        "{%0,%1,%2,%3}, {%4,%5,%6,%7}, {%8,%9}, {%0,%1,%2,%3};"
        : "+f"(c[0]), "+f"(c[1]), "+f"(c[2]), "+f"(c[3])
        : "r"(a[0]), "r"(a[1]), "r"(a[2]), "r"(a[3]), "r"(b0), "r"(b1));
}
__device__ __forceinline__ uint32_t sw128(uint32_t off) {
    return off ^ ((off >> 3) & 0x70);
}

// ---------------------------------------------------------------------------
// Scan + compact fused: one block of 1024 threads handles both batches.
// ---------------------------------------------------------------------------
__global__ void scan_compact_kernel(const int* __restrict__ loc) {
    __shared__ int s[1024];
    int tid = threadIdx.x;
    if (tid == 0) g_nact = 0;
    __syncthreads();
    for (int b = 0; b < BATCH; b++) {
        const int* L = loc + b * NTXT;
        int a0 = L[2 * tid];
        int a1 = L[2 * tid + 1];
        int v0 = a0, v1 = a0 + a1;
        s[tid] = v1;
        __syncthreads();
        for (int off = 1; off < 1024; off <<= 1) {
            int t = (tid >= off) ? s[tid - off] : 0;
            __syncthreads();
            s[tid] += t;
            __syncthreads();
        }
        int excl = s[tid] - v1;
        int t0 = excl + v0, t1 = excl + v1;
        int r0 = b * NTXT + 2 * tid, r1 = r0 + 1;
        g_tt[r0] = t0;
        g_tt[r1] = t1;
        if (t0 >= 1 && t0 <= T_MEDIA) g_act[atomicAdd(&g_nact, 1)] = r0;
        if (t1 >= 1 && t1 <= T_MEDIA) g_act[atomicAdd(&g_nact, 1)] = r1;
        __syncthreads();
    }
}

// ---------------------------------------------------------------------------
// Block reduce helper (256 threads)
// ---------------------------------------------------------------------------
__device__ __forceinline__ float blockReduceSum256(float v, float* red) {
    #pragma unroll
    for (int o = 16; o; o >>= 1) v += __shfl_xor_sync(0xffffffffu, v, o);
    int lane = threadIdx.x & 31, w = threadIdx.x >> 5;
    if (lane == 0) red[w] = v;
    __syncthreads();
    float r = (threadIdx.x < 8) ? red[threadIdx.x] : 0.0f;
    if (threadIdx.x < 32) {
        #pragma unroll
        for (int o = 4; o; o >>= 1) r += __shfl_xor_sync(0xffffffffu, r, o);
        if (threadIdx.x == 0) red[0] = r;
    }
    __syncthreads();
    float out = red[0];
    __syncthreads();
    return out;
}

// ---------------------------------------------------------------------------
// image fp32 -> fp16 (elementwise)
// ---------------------------------------------------------------------------
__global__ void conv_img(const float* __restrict__ img) {
    size_t i = ((size_t)blockIdx.x * 256 + threadIdx.x) * 4;
    float4 v = *(const float4*)(img + i);
    *(__half2*)(g_img_h + i)     = __halves2half2(__float2half_rn(v.x), __float2half_rn(v.y));
    *(__half2*)(g_img_h + i + 2) = __halves2half2(__float2half_rn(v.z), __float2half_rn(v.w));
}

// ---------------------------------------------------------------------------
// Wkv [K,N] fp32 -> W^T [N,K] fp16 (tiled transpose)
// ---------------------------------------------------------------------------
__global__ void wtrans(const float* __restrict__ W,
                       __half* __restrict__ Th,
                       int Kd, int Nd) {
    __shared__ float t[32][33];
    int bx = blockIdx.x * 32;
    int by = blockIdx.y * 32;
    int x = threadIdx.x & 31, y4 = (threadIdx.x >> 5) * 4;
    #pragma unroll
    for (int i = 0; i < 4; i++)
        t[y4 + i][x] = W[(size_t)(by + y4 + i) * Nd + bx + x];
    __syncthreads();
    #pragma unroll
    for (int i = 0; i < 4; i++) {
        size_t o = (size_t)(bx + y4 + i) * Kd + by + x;
        Th[o] = __float2half_rn(t[x][y4 + i]);
    }
}

// ---------------------------------------------------------------------------
// fp16 GEMM via mma.sync (HMMA), 4-stage cp.async pipeline,
// one barrier per ktile (R14-proven inner loop).  C = A @ B^T, KTILES = 16.
// CTA tile 128x256, 8 warps at 64x64.
// ---------------------------------------------------------------------------
#define GBM 128
#define GBN 256
#define GBK 64
#define KTILES 16
#define ABYTES (GBM * GBK * 2)                // 16384
#define BBYTES (GBN * GBK * 2)                // 32768
#define STG    4
#define SMEM_GEMM (STG * (ABYTES + BBYTES))   // 196608

__global__ __launch_bounds__(256, 1)
void gemm_hmma(const __half* __restrict__ A,
               const __half* __restrict__ B,
               float* __restrict__ C, int N) {
    extern __shared__ char smem[];
    const int K = 1024;
    uint32_t sb = smem_u32(smem);
    int tid = threadIdx.x;
    int lane = tid & 31, wid = tid >> 5;
    int row0 = blockIdx.y * GBM, col0 = blockIdx.x * GBN;

    int lr = tid >> 3;
    int lc = tid & 7;

    int wm = wid >> 2, wn = wid & 3;
    int m_warp = wm * 64, n_warp = wn * 64;
    int a_row = lane & 15;
    int a_colb = (lane >> 4) * 8;
    int b_row = (lane & 7) + 8 * ((lane >> 4) & 1);
    int b_colb = 8 * ((lane >> 3) & 1);

    float acc[4][8][4];
    #pragma unroll
    for (int i = 0; i < 4; i++)
        #pragma unroll
        for (int j = 0; j < 8; j++)
            #pragma unroll
            for (int q = 0; q < 4; q++) acc[i][j][q] = 0.0f;

    auto issue = [&](int kt) {
        int ks = kt * GBK;
        uint32_t abase = sb + (uint32_t)((kt % STG) * (ABYTES + BBYTES));
        uint32_t bbase = abase + ABYTES;
        #pragma unroll
        for (int j = 0; j < 4; j++) {
            int r = lr + 32 * j;
            uint32_t off = (uint32_t)(r * 128 + lc * 16);
            cp_async16(abase + sw128(off),
                       A + (size_t)(row0 + r) * K + ks + lc * 8);
        }
        #pragma unroll
        for (int j = 0; j < 8; j++) {
            int r = lr + 32 * j;
            uint32_t off = (uint32_t)(r * 128 + lc * 16);
            cp_async16(bbase + sw128(off),
                       B + (size_t)(col0 + r) * K + ks + lc * 8);
        }
        asm volatile("cp.async.commit_group;" ::: "memory");
    };

    issue(0);
    issue(1);
    issue(2);

    #pragma unroll 1
    for (int kt = 0; kt < KTILES; kt++) {
        if (kt + 1 < KTILES) {
            asm volatile("cp.async.wait_group 2;" ::: "memory");
        } else {
            asm volatile("cp.async.wait_group 0;" ::: "memory");
        }
        __syncthreads();

        uint32_t ab = sb + (uint32_t)((kt % STG) * (ABYTES + BBYTES));
        uint32_t bb = ab + ABYTES;
        #pragma unroll
        for (int k16 = 0; k16 < 4; k16++) {
            uint32_t a_r[4][4], b_r[4][4];
            #pragma unroll
            for (int mf = 0; mf < 4; mf++) {
                uint32_t off = (uint32_t)((m_warp + mf * 16 + a_row) * 128 +
                                          (k16 * 16 + a_colb) * 2);
                ldsm4(a_r[mf], ab + sw128(off));
            }
            #pragma unroll
            for (int nf2 = 0; nf2 < 4; nf2++) {
                uint32_t off = (uint32_t)((n_warp + nf2 * 16 + b_row) * 128 +
                                          (k16 * 16 + b_colb) * 2);
                ldsm4(b_r[nf2], bb + sw128(off));
            }
            #pragma unroll
            for (int mf = 0; mf < 4; mf++)
                #pragma unroll
                for (int nf = 0; nf < 8; nf++) {
                    const uint32_t* b2 = &b_r[nf >> 1][(nf & 1) * 2];
                    mma16816h(acc[mf][nf], a_r[mf], b2[0], b2[1]);
                }
        }

        if (kt + 3 < KTILES) issue(kt + 3);
    }

    // ---- epilogue: store C ----
    int r_base = row0 + m_warp + (lane >> 2);
    int c_base = col0 + n_warp + 2 * (lane & 3);
    #pragma unroll
    for (int mf = 0; mf < 4; mf++)
        #pragma unroll
        for (int nf = 0; nf < 8; nf++) {
            float* p = C + (size_t)(r_base + mf * 16) * N + c_base + nf * 8;
            *(float2*)p = make_float2(acc[mf][nf][0], acc[mf][nf][1]);
            *(float2*)(p + (size_t)8 * N) = make_float2(acc[mf][nf][2], acc[mf][nf][3]);
        }
}

// ---------------------------------------------------------------------------
// image column partial sums + mean (exact fp32 vmean path)
// ---------------------------------------------------------------------------
__global__ void imgmean_part(const float* __restrict__ image) {
    int c  = blockIdx.x * 256 + threadIdx.x;
    int ry = blockIdx.y;                    // 0..31
    int b  = blockIdx.z;
    const float* base = image + ((size_t)(b * TM_TOT + ry * 32)) * DIM + c;
    float s = 0.0f;
    #pragma unroll 8
    for (int j = 0; j < 32; j++) s += base[(size_t)j * DIM];
    g_impart[(b * 32 + ry) * DIM + c] = s;
}

__global__ void imgmean_final() {
    int c = blockIdx.x * 256 + threadIdx.x;
    int b = blockIdx.y;
    float s = 0.0f;
    #pragma unroll
    for (int r = 0; r < 32; r++) s += g_impart[(b * 32 + r) * DIM + c];
    g_impart[b * 32 * DIM + c] = s * (1.0f / TM_TOT);   // row 0 holds imgmean
}

// vmean[b] = imgmean[b] @ Wv  (Wv = Wkv cols [1024,2048), ldw 2048) — exact
__global__ __launch_bounds__(256)
void vmean_kernel(const float* __restrict__ Wkv) {
    __shared__ float x[DIM];
    __shared__ float part[8 * 64];
    int tid = threadIdx.x, lane = tid & 31, w = tid >> 5;
    int n0 = blockIdx.x * 64;
    int b = blockIdx.y;
    ((float4*)x)[tid] = ((const float4*)(g_impart + b * 32 * DIM))[tid];
    __syncthreads();
    {
        float a0 = 0.0f, a1 = 0.0f;
        int n = n0 + lane * 2;
        const float* Wp = Wkv + (size_t)(w * 128) * (2 * DIM) + DIM + n;
        const float* xp = x + w * 128;
        #pragma unroll 8
        for (int kk = 0; kk < 128; kk++) {
            float xv = xp[kk];
            float2 wv = *(const float2*)(Wp + (size_t)kk * (2 * DIM));
            a0 = fmaf(xv, wv.x, a0);
            a1 = fmaf(xv, wv.y, a1);
        }
        part[w * 64 + lane * 2]     = a0;
        part[w * 64 + lane * 2 + 1] = a1;
    }
    __syncthreads();
    if (tid < 64) {
        float acc = 0.0f;
        #pragma unroll
        for (int ww = 0; ww < 8; ww++) acc += part[ww * 64 + tid];
        g_vmean[b * DIM + n0 + tid] = acc;
    }
}

// omean[b] = vmean[b] @ Wo — exact
__global__ __launch_bounds__(256)
void omean_kernel(const float* __restrict__ Wo) {
    __shared__ float x[DIM];
    __shared__ float part[8 * 64];
    int tid = threadIdx.x, lane = tid & 31, w = tid >> 5;
    int n0 = blockIdx.x * 64;
    int b = blockIdx.y;
    ((float4*)x)[tid] = ((const float4*)(g_vmean + b * DIM))[tid];
    __syncthreads();
    {
        float a0 = 0.0f, a1 = 0.0f;
        int n = n0 + lane * 2;
        const float* Wp = Wo + (size_t)(w * 128) * DIM + n;
        const float* xp = x + w * 128;
        #pragma unroll 8
        for (int kk = 0; kk < 128; kk++) {
            float xv = xp[kk];
            float2 wv = *(const float2*)(Wp + (size_t)kk * DIM);
            a0 = fmaf(xv, wv.x, a0);
            a1 = fmaf(xv, wv.y, a1);
        }
        part[w * 64 + lane * 2]     = a0;
        part[w * 64 + lane * 2 + 1] = a1;
    }
    __syncthreads();
    if (tid < 64) {
        float acc = 0.0f;
        #pragma unroll
        for (int ww = 0; ww < 8; ww++) acc += part[ww * 64 + tid];
        g_omean[b * DIM + n0 + tid] = acc;
    }
}

// ---------------------------------------------------------------------------
// Slot-batched fused LayerNorm + q GEMV.  grid (16 n-chunks, 8 slot-groups).
// ---------------------------------------------------------------------------
__global__ __launch_bounds__(256)
void qact_kernel(const float* __restrict__ text,
                 const float* __restrict__ gamma,
                 const float* __restrict__ beta,
                 const float* __restrict__ Wq) {
    __shared__ float xs[SB][DIM];      // 16 KB
    __shared__ float red[8];
    __shared__ float part[8 * 64];
    int tid = threadIdx.x, lane = tid & 31, w = tid >> 5;
    int n0 = blockIdx.x * 64;
    int nact = g_nact;

    for (int s0 = blockIdx.y * SB; s0 < nact; s0 += gridDim.y * SB) {
        int ns = min(SB, nact - s0);
        for (int si = 0; si < ns; si++) {
            int row = g_act[s0 + si];
            float4 v = ((const float4*)(text + (size_t)row * DIM))[tid];
            float sm = v.x + v.y + v.z + v.w;
            float mu = blockReduceSum256(sm, red) * (1.0f / DIM);
            float dx = v.x - mu, dy = v.y - mu, dz = v.z - mu, dw = v.w - mu;
            float var = blockReduceSum256(dx * dx + dy * dy + dz * dz + dw * dw, red)
                      * (1.0f / DIM);
            float inv = rsqrtf(var + EPS);
            float4 g = ((const float4*)gamma)[tid];
            float4 bt = ((const float4*)beta)[tid];
            xs[si][4 * tid + 0] = dx * inv * g.x + bt.x;
            xs[si][4 * tid + 1] = dy * inv * g.y + bt.y;
            xs[si][4 * tid + 2] = dz * inv * g.z + bt.z;
            xs[si][4 * tid + 3] = dw * inv * g.w + bt.w;
        }
        for (int si = ns; si < SB; si++) {
            xs[si][4 * tid + 0] = 0.f; xs[si][4 * tid + 1] = 0.f;
            xs[si][4 * tid + 2] = 0.f; xs[si][4 * tid + 3] = 0.f;
        }
        __syncthreads();

        float a0[SB], a1[SB];
        #pragma unroll
        for (int si = 0; si < SB; si++) { a0[si] = 0.f; a1[si] = 0.f; }
        int n = n0 + lane * 2;
        const float* Wp = Wq + (size_t)(w * 128) * DIM + n;
        #pragma unroll 4
        for (int kk = 0; kk < 128; kk++) {
            float2 wv = *(const float2*)(Wp + (size_t)kk * DIM);
            #pragma unroll
            for (int si = 0; si < SB; si++) {
                float xv = xs[si][w * 128 + kk];
                a0[si] = fmaf(xv, wv.x, a0[si]);
                a1[si] = fmaf(xv, wv.y, a1[si]);
            }
        }
        for (int si = 0; si < ns; si++) {
            part[w * 64 + lane * 2]     = a0[si];
            part[w * 64 + lane * 2 + 1] = a1[si];
            __syncthreads();
            if (tid < 64) {
                float acc = 0.0f;
                #pragma unroll
                for (int ww = 0; ww < 8; ww++) acc += part[ww * 64 + tid];
                g_qact[(size_t)(s0 + si) * DIM + n0 + tid] = acc;
            }
            __syncthreads();
        }
    }
}

// ---------------------------------------------------------------------------
// Segment attention per (slot, head-group of 2 heads). grid (64, 8).
// ---------------------------------------------------------------------------
__global__ __launch_bounds__(256)
void attn_act_kernel() {
    __shared__ float qs[128];
    __shared__ float S[2][M_MEDIA];
    __shared__ float part[8][128];
    int tid = threadIdx.x;
    int lane = tid & 31, w = tid >> 5;
    int hg = blockIdx.y;               // 0..7 (2 heads each)
    int nact = g_nact;

    for (int s = blockIdx.x; s < nact; s += gridDim.x) {
        int row = g_act[s];
        int b = row >> 11;
        int tt = g_tt[row];
        int j0 = (tt - 1) * M_MEDIA;

        if (tid < 128) qs[tid] = g_qact[(size_t)s * DIM + hg * 128 + tid];
        __syncthreads();

        int h = lane >> 4;
        int cc = (lane & 15) * 4;
        {
            const float scale = 0.125f;
            const float* qh = qs + h * 64 + cc;
            float q0 = qh[0], q1 = qh[1], q2 = qh[2], q3 = qh[3];
            const float* kbase = g_kv + ((size_t)(b * TM_TOT + j0 + w * 32)) * (2 * DIM)
                               + hg * 128 + h * 64 + cc;
            for (int jj = 0; jj < 32; jj++) {
                float4 k4 = *(const float4*)(kbase + (size_t)jj * (2 * DIM));
                float p = k4.x * q0 + k4.y * q1 + k4.z * q2 + k4.w * q3;
                p += __shfl_xor_sync(0xffffffffu, p, 8);
                p += __shfl_xor_sync(0xffffffffu, p, 4);
                p += __shfl_xor_sync(0xffffffffu, p, 2);
                p += __shfl_xor_sync(0xffffffffu, p, 1);
                if ((lane & 15) == 0) S[h][w * 32 + jj] = p * scale;
            }
        }
        __syncthreads();

        if (w < 2) {
            float vals[8];
            float m = -1e30f;
            #pragma unroll
            for (int k = 0; k < 8; k++) {
                vals[k] = S[w][lane + 32 * k];
                m = fmaxf(m, vals[k]);
            }
            #pragma unroll
            for (int o = 16; o; o >>= 1) m = fmaxf(m, __shfl_xor_sync(0xffffffffu, m, o));
            float sum = 0.0f;
            #pragma unroll
            for (int k = 0; k < 8; k++) { vals[k] = __expf(vals[k] - m); sum += vals[k]; }
            #pragma unroll
            for (int o = 16; o; o >>= 1) sum += __shfl_xor_sync(0xffffffffu, sum, o);
            float inv = 1.0f / sum;
            #pragma unroll
            for (int k = 0; k < 8; k++) S[w][lane + 32 * k] = vals[k] * inv;
        }
        __syncthreads();

        {
            float acc[4] = {0.f, 0.f, 0.f, 0.f};
            const float* vbase = g_kv + ((size_t)(b * TM_TOT + j0 + w * 32)) * (2 * DIM)
                               + DIM + hg * 128 + h * 64 + cc;
            #pragma unroll 4
            for (int jj = 0; jj < 32; jj++) {
                float p = S[h][w * 32 + jj];
                float4 v4 = *(const float4*)(vbase + (size_t)jj * (2 * DIM));
                acc[0] = fmaf(p, v4.x, acc[0]);
                acc[1] = fmaf(p, v4.y, acc[1]);
                acc[2] = fmaf(p, v4.z, acc[2]);
                acc[3] = fmaf(p, v4.w, acc[3]);
            }
            #pragma unroll
            for (int u = 0; u < 4; u++) part[w][h * 64 + cc + u] = acc[u];
        }
        __syncthreads();

        if (tid < 128) {
            float a = 0.0f;
            #pragma unroll
            for (int ww = 0; ww < 8; ww++) a += part[ww][tid];
            g_oact[(size_t)s * DIM + hg * 128 + tid] = a;
        }
        __syncthreads();
    }
}

// ---------------------------------------------------------------------------
// Fill output: tt==0 -> 0, tt>4 -> omean, active rows skipped
// ---------------------------------------------------------------------------
__global__ void fill_kernel(float* __restrict__ out) {
    int row = blockIdx.x;
    int tt = g_tt[row];
    if (tt >= 1 && tt <= T_MEDIA) return;
    int tid = threadIdx.x;
    int b = row >> 11;
    float4 val = (tt == 0) ? make_float4(0.f, 0.f, 0.f, 0.f)
                           : ((const float4*)(g_omean + b * DIM))[tid];
    ((float4*)(out + (size_t)row * DIM))[tid] = val;
}

// ---------------------------------------------------------------------------
// Slot-batched out GEMV: out[row] = oact[s] @ Wo.  grid (16, 8), SBO=4.
// ---------------------------------------------------------------------------
__global__ __launch_bounds__(256)
void out_act_kernel(const float* __restrict__ Wo, float* __restrict__ out) {
    __shared__ float xs[SBO][DIM];     // 16 KB
    __shared__ float part[8 * 64];
    int tid = threadIdx.x, lane = tid & 31, w = tid >> 5;
    int n0 = blockIdx.x * 64;
    int nact = g_nact;

    for (int s0 = blockIdx.y * SBO; s0 < nact; s0 += gridDim.y * SBO) {
        int ns = min(SBO, nact - s0);
        for (int si = 0; si < ns; si++)
            ((float4*)xs[si])[tid] = ((const float4*)(g_oact + (size_t)(s0 + si) * DIM))[tid];
        for (int si = ns; si < SBO; si++) {
            xs[si][4 * tid + 0] = 0.f; xs[si][4 * tid + 1] = 0.f;
            xs[si][4 * tid + 2] = 0.f; xs[si][4 * tid + 3] = 0.f;
        }
        __syncthreads();

        float a0[SBO], a1[SBO];
        #pragma unroll
        for (int si = 0; si < SBO; si++) { a0[si] = 0.f; a1[si] = 0.f; }
        int n = n0 + lane * 2;
        const float* Wp = Wo + (size_t)(w * 128) * DIM + n;
        #pragma unroll 4
        for (int kk = 0; kk < 128; kk++) {
            float2 wv = *(const float2*)(Wp + (size_t)kk * DIM);
            #pragma unroll
            for (int si = 0; si < SBO; si++) {
                float xv = xs[si][w * 128 + kk];
                a0[si] = fmaf(xv, wv.x, a0[si]);
                a1[si] = fmaf(xv, wv.y, a1[si]);
            }
        }
        for (int si = 0; si < ns; si++) {
            part[w * 64 + lane * 2]     = a0[si];
            part[w * 64 + lane * 2 + 1] = a1[si];
            __syncthreads();
            if (tid < 64) {
                float acc = 0.0f;
                #pragma unroll
                for (int ww = 0; ww < 8; ww++) acc += part[ww * 64 + tid];
                out[(size_t)g_act[s0 + si] * DIM + n0 + tid] = acc;
            }
            __syncthreads();
        }
    }
}

// ---------------------------------------------------------------------------
// Launch — two streams.
// main: conv -> GEMM -> attn -> out_act
// s2:   wtrans(evW) -> scan -> qact(evJoin) -> imgmean chain -> omean -> fill
// ---------------------------------------------------------------------------
extern "C" void kernel_launch(void* const* d_in, const int* in_sizes, int n_in,
                              void* d_out, int out_size) {
    const float* text  = (const float*)d_in[0];
    const float* image = (const float*)d_in[1];
    const int*   loc   = (const int*)d_in[2];
    const float* Wq    = (const float*)d_in[3];
    const float* Wkv   = (const float*)d_in[4];
    const float* Wo    = (const float*)d_in[5];
    const float* gamma = (const float*)d_in[6];
    const float* beta  = (const float*)d_in[7];
    float* out = (float*)d_out;

    static cudaStream_t s2 = nullptr;
    static cudaEvent_t evFork = nullptr, evW = nullptr, evJoin = nullptr, evFill = nullptr;
    static int inited = 0;
    if (!inited) {
        cudaFuncSetAttribute(gemm_hmma,
                             cudaFuncAttributeMaxDynamicSharedMemorySize, SMEM_GEMM);
        cudaStreamCreateWithFlags(&s2, cudaStreamNonBlocking);
        cudaEventCreateWithFlags(&evFork, cudaEventDisableTiming);
        cudaEventCreateWithFlags(&evW, cudaEventDisableTiming);
        cudaEventCreateWithFlags(&evJoin, cudaEventDisableTiming);
        cudaEventCreateWithFlags(&evFill, cudaEventDisableTiming);
        inited = 1;
    }

    __half *img_h, *wkv_h;
    float *p_kv;
    cudaGetSymbolAddress((void**)&img_h, g_img_h);
    cudaGetSymbolAddress((void**)&wkv_h, g_Wkv_h);
    cudaGetSymbolAddress((void**)&p_kv,  g_kv);

    cudaEventRecord(evFork, 0);
    cudaStreamWaitEvent(s2, evFork, 0);

    // s2: wtrans (feeds GEMM)
    wtrans<<<dim3(2 * DIM / 32, DIM / 32), 256, 0, s2>>>(Wkv, wkv_h, DIM, 2 * DIM);
    cudaEventRecord(evW, s2);

    // main: conv, then GEMM (needs wtrans)
    conv_img<<<(MKV * DIM) / (256 * 4), 256>>>(image);
    cudaStreamWaitEvent(0, evW, 0);
    gemm_hmma<<<dim3(2 * DIM / GBN, MKV / GBM), 256, SMEM_GEMM>>>(
        img_h, wkv_h, p_kv, 2 * DIM);

    // s2: q-branch (overlaps GEMM), then the exact mean chain + fill
    scan_compact_kernel<<<1, 1024, 0, s2>>>(loc);
    qact_kernel<<<dim3(16, 8), 256, 0, s2>>>(text, gamma, beta, Wq);
    cudaEventRecord(evJoin, s2);
    imgmean_part<<<dim3(DIM / 256, 32, BATCH), 256, 0, s2>>>(image);
    imgmean_final<<<dim3(DIM / 256, BATCH), 256, 0, s2>>>();
    vmean_kernel<<<dim3(16, BATCH), 256, 0, s2>>>(Wkv);
    omean_kernel<<<dim3(16, BATCH), 256, 0, s2>>>(Wo);
    fill_kernel<<<MQ, 256, 0, s2>>>(out);
    cudaEventRecord(evFill, s2);

    // main: join q-branch, then attention tail
    cudaStreamWaitEvent(0, evJoin, 0);
    attn_act_kernel<<<dim3(64, 8), 256>>>();
    out_act_kernel<<<dim3(16, 8), 256>>>(Wo, out);
    cudaStreamWaitEvent(0, evFill, 0);
}